// round 12
// baseline (speedup 1.0000x reference)
#include <cuda_runtime.h>
#include <cstdint>

#define Bsz 128
#define Lseq 1024
#define Hd 256
#define G3 768
#define FBLK 128
#define W2S 258

typedef unsigned long long u64;

__device__ __forceinline__ u64 f2fma(u64 a, u64 b, u64 c) {
    u64 d; asm("fma.rn.f32x2 %0, %1, %2, %3;" : "=l"(d) : "l"(a), "l"(b), "l"(c)); return d;
}
__device__ __forceinline__ u64 f2add(u64 a, u64 b) {
    u64 d; asm("add.rn.f32x2 %0, %1, %2;" : "=l"(d) : "l"(a), "l"(b)); return d;
}
__device__ __forceinline__ u64 dup2(float x) {
    u64 r; asm("mov.b64 %0, {%1, %1};" : "=l"(r) : "f"(x)); return r;
}
__device__ __forceinline__ void up2(u64 v, float& lo, float& hi) {
    asm("mov.b64 {%0, %1}, %2;" : "=f"(lo), "=f"(hi) : "l"(v));
}

// ---------------- scratch ----------------
__device__ float g_gi[(size_t)Lseq * G3 * Bsz];      // [t][3H][B] (layer-0 gi)
__device__ float g_hseq0[(size_t)Lseq * Hd * Bsz];   // [t][k][b]
__device__ float g_hseq1[(size_t)Lseq * Hd * Bsz];
__device__ float g_h1init[Hd * Bsz];                 // [k][b]

__device__ unsigned g_flagA[4 * 32 * 32];
__device__ unsigned g_flagB[4 * 32 * 32];
__device__ unsigned g_cnt[32];
__device__ unsigned g_gen[32];

// ---------------- input-side GEMM (layer 0): Gi[t][c][b] ----------------
__global__ __launch_bounds__(256) void gi_gemm_kernel(
    const float* __restrict__ xin, const float* __restrict__ W,
    const float* __restrict__ bias)
{
    __shared__ float Ws[16 * 132];
    __shared__ float As[16 * 132];

    const int t  = blockIdx.y;
    const int c0 = blockIdx.x * 128;
    const int tid = threadIdx.x;
    const int ty = tid >> 4;
    const int tx = tid & 15;

    u64 acc2[8][4];
#pragma unroll
    for (int i = 0; i < 8; i++)
#pragma unroll
        for (int j = 0; j < 4; j++) acc2[i][j] = 0ull;

    for (int k0 = 0; k0 < 256; k0 += 16) {
        {
            int row  = tid >> 2;
            int col4 = (tid & 3) * 4;
#pragma unroll
            for (int it = 0; it < 2; it++, row += 64) {
                float4 w = *(const float4*)(W + (size_t)(c0 + row) * 256 + k0 + col4);
                Ws[(col4 + 0) * 132 + row] = w.x;
                Ws[(col4 + 1) * 132 + row] = w.y;
                Ws[(col4 + 2) * 132 + row] = w.z;
                Ws[(col4 + 3) * 132 + row] = w.w;
            }
        }
        {
            int row  = tid >> 2;
            int col4 = (tid & 3) * 4;
#pragma unroll
            for (int it = 0; it < 2; it++, row += 64) {
                float4 a = *(const float4*)(xin + ((size_t)row * Lseq + t) * 256 + k0 + col4);
                As[(col4 + 0) * 132 + row] = a.x;
                As[(col4 + 1) * 132 + row] = a.y;
                As[(col4 + 2) * 132 + row] = a.z;
                As[(col4 + 3) * 132 + row] = a.w;
            }
        }
        __syncthreads();

#pragma unroll
        for (int kk = 0; kk < 16; kk++) {
            float wr[8];
            *(float4*)(wr)     = *(const float4*)(Ws + kk * 132 + ty * 4);
            *(float4*)(wr + 4) = *(const float4*)(Ws + kk * 132 + 64 + ty * 4);
            ulonglong2 aA = *(const ulonglong2*)(As + kk * 132 + tx * 4);
            ulonglong2 aB = *(const ulonglong2*)(As + kk * 132 + 64 + tx * 4);
#pragma unroll
            for (int i = 0; i < 8; i++) {
                u64 wd = dup2(wr[i]);
                acc2[i][0] = f2fma(aA.x, wd, acc2[i][0]);
                acc2[i][1] = f2fma(aA.y, wd, acc2[i][1]);
                acc2[i][2] = f2fma(aB.x, wd, acc2[i][2]);
                acc2[i][3] = f2fma(aB.y, wd, acc2[i][3]);
            }
        }
        __syncthreads();
    }

    float* gout = g_gi + (size_t)t * G3 * Bsz;
#pragma unroll
    for (int i = 0; i < 8; i++) {
        int c = (i < 4) ? (c0 + ty * 4 + i) : (c0 + 64 + ty * 4 + (i - 4));
        float bv = bias[c];
        float a0, a1, a2, a3, a4, a5, a6, a7;
        up2(acc2[i][0], a0, a1); up2(acc2[i][1], a2, a3);
        up2(acc2[i][2], a4, a5); up2(acc2[i][3], a6, a7);
        *(float4*)(gout + (size_t)c * Bsz + tx * 4) =
            make_float4(a0 + bv, a1 + bv, a2 + bv, a3 + bv);
        *(float4*)(gout + (size_t)c * Bsz + 64 + tx * 4) =
            make_float4(a4 + bv, a5 + bv, a6 + bv, a7 + bv);
    }
}

#define BARA() asm volatile("bar.sync 1, 512;" ::: "memory")
#define BARB() asm volatile("bar.sync 2, 512;" ::: "memory")

// ---------------- fused two-layer recurrence, warp-specialized ----------------
// 128 blocks x 1024 threads (1/SM). Warps 0-15: layer 0 (R11 dataflow code).
// Warps 16-31: layer 1 (computes gi1 + gh1 in-loop, h via L2 direct loads).
__global__ __launch_bounds__(1024) void gru_fused_kernel(
    const float* __restrict__ w_hh0, const float* __restrict__ b_hh0,
    const float* __restrict__ w_ih1, const float* __restrict__ w_hh1,
    const float* __restrict__ b_ih1, const float* __restrict__ b_hh1,
    const float* __restrict__ h0all)
{
    extern __shared__ __align__(16) char smraw[];
    u64*   w2A   = (u64*)smraw;                      // 6192 u64
    u64*   redA  = w2A + 6192;                       // 3072 u64
    u64*   redB  = redA + 3072;                      // 6144 u64
    float* wB    = (float*)(redB + 6144);            // 12480 f
    float* h_sA  = wB + 12480;                       // 8192 f
    float* red2A = h_sA + 8192;                      // 768 f
    float* red2B = red2A + 768;                      // 1536 f
    float* bhA   = red2B + 1536;                     // 32 f
    float* bhB   = bhA + 32;                         // 32 f
    volatile unsigned* smflagA = (volatile unsigned*)(bhB + 32);  // 32 u32

    const int tid = threadIdx.x;
    const int bt = blockIdx.x >> 5;
    const int ht = blockIdx.x & 31;
    const int b0 = bt * 32;
    const int j0 = ht * 8;

    unsigned* myflagA = &g_flagA[(bt * 32 + ht) * 32];
    unsigned* myflagB = &g_flagB[(bt * 32 + ht) * 32];

    if (tid == 0)
        asm volatile("st.relaxed.gpu.u32 [%0], %1;" :: "l"(myflagA), "r"(0u) : "memory");
    if (tid == 1)
        asm volatile("st.relaxed.gpu.u32 [%0], %1;" :: "l"(myflagB), "r"(0u) : "memory");
    if (tid < 32) smflagA[tid] = 0u;

    // ---- stage A weights (duplicated f32x2 over batch) ----
    for (int i = tid; i < 6144; i += 1024) {
        int gj = i >> 8, k = i & 255;
        int g = gj >> 3, j = gj & 7;
        w2A[gj * W2S + k] = dup2(__ldg(w_hh0 + (size_t)(g * 256 + j0 + j) * 256 + k));
    }
    if (tid < 24) bhA[tid] = b_hh0[(tid >> 3) * 256 + j0 + (tid & 7)];

    // ---- stage B weights (plain floats): rows 0-23 = ih r/z/n, 24-47 = hh r/z/n ----
    for (int i = tid; i < 48 * 256; i += 1024) {
        int row = i >> 8, k = i & 255;
        int m = row >> 3, jl = row & 7, jg = j0 + jl;
        const float* s = (m < 3) ? (w_ih1 + (size_t)(m * 256 + jg) * 256)
                                 : (w_hh1 + (size_t)((m - 3) * 256 + jg) * 256);
        wB[row * 260 + k] = s[k];
    }
    if (tid < 8) {
        int jg = j0 + tid;
        bhB[tid]      = b_ih1[jg] + b_hh1[jg];
        bhB[8 + tid]  = b_ih1[256 + jg] + b_hh1[256 + jg];
        bhB[16 + tid] = b_ih1[512 + jg];
        bhB[24 + tid] = b_hh1[512 + jg];
    }
    // ---- transpose layer-1 h0 into g_h1init[k][b] (same values from all ht; benign) ----
    for (int i = tid; i < 8192; i += 1024) {
        int k = i >> 5, bb = i & 31;
        g_h1init[k * 128 + b0 + bb] = h0all[(size_t)Bsz * Hd + (size_t)(b0 + bb) * 256 + k];
    }
    __syncthreads();

    // ---- global init barrier ----
    {
        unsigned gen;
        asm volatile("ld.acquire.gpu.u32 %0, [%1];" : "=r"(gen) : "l"(&g_gen[0]) : "memory");
        unsigned target = gen + 1;
        if (tid == 0) {
            unsigned old;
            asm volatile("atom.release.gpu.add.u32 %0, [%1], %2;"
                         : "=r"(old) : "l"(&g_cnt[0]), "r"(1u) : "memory");
            if (old == FBLK - 1u) {
                asm volatile("st.relaxed.gpu.u32 [%0], %1;" :: "l"(&g_cnt[0]), "r"(0u) : "memory");
                asm volatile("st.release.gpu.u32 [%0], %1;" :: "l"(&g_gen[0]), "r"(target) : "memory");
            }
            unsigned v;
            do {
                asm volatile("ld.acquire.gpu.u32 %0, [%1];" : "=r"(v) : "l"(&g_gen[0]) : "memory");
            } while (v < target);
        }
        __syncthreads();
    }

    if (tid < 512) {
        // ================= A team: layer 0 (R11 dataflow) =================
        const int a = tid;
        const int bq = a & 7;
        const int j  = (a >> 3) & 7;
        const int kq = a >> 6;
        const int kbase = kq * 32;
        const int warp = a >> 5;
        const int lane = a & 31;

        const u64* wrp = w2A + (0 + j) * W2S + kbase;
        const u64* wzp = w2A + (8 + j) * W2S + kbase;
        const u64* wnp = w2A + (16 + j) * W2S + kbase;
        const float* hb = h_sA + kbase * 32 + bq * 4;

        const int ab = a & 31;
        const int aj = (a >> 5) & 7;
        const size_t gidx = (size_t)(j0 + aj) * Bsz + b0 + ab;

        float cir = 0.f, ciz = 0.f, cin_ = 0.f;
        if (a < 256) {
            cir  = __ldg(g_gi + gidx);
            ciz  = __ldg(g_gi + 32768 + gidx);
            cin_ = __ldg(g_gi + 65536 + gidx);
        }

        for (int t = 0; t < Lseq; t++) {
            if (t == 0) {
                for (int i = a; i < 8192; i += 512) {
                    int k = i >> 5, bb = i & 31;
                    h_sA[k * 32 + bb] = h0all[(size_t)(b0 + bb) * 256 + k];
                }
                BARA();
            } else {
                const float* src = g_hseq0 + (size_t)(t - 1) * 32768;
                const int kq_w = warp >> 1;
#pragma unroll
                for (int e = 0; e < 2; e++) {
                    int c = kq_w * 4 + (warp & 1) * 2 + e;
                    const unsigned* fp = &g_flagA[(bt * 32 + c) * 32];
                    unsigned v;
                    do {
                        asm volatile("ld.acquire.gpu.u32 %0, [%1];" : "=r"(v) : "l"(fp) : "memory");
                    } while (v < (unsigned)t);
                    int k   = c * 8 + (lane >> 2);
                    int col = (lane & 3) * 4;
                    const float* sp = src + (size_t)k * Bsz + b0;
                    float4 v0 = *(const float4*)(sp + col);
                    float4 v1 = *(const float4*)(sp + col + 16);
                    *(float4*)(h_sA + k * 32 + col)      = v0;
                    *(float4*)(h_sA + k * 32 + col + 16) = v1;
                    __syncwarp();
                    __threadfence_block();
                    if (lane == 0) smflagA[c] = (unsigned)t;
                }
#pragma unroll
                for (int e = 0; e < 4; e++) {
                    int c = kq * 4 + e;
                    while (smflagA[c] < (unsigned)t) { }
                }
                __threadfence_block();
            }

            u64 ar0 = 0, ar1 = 0, az0 = 0, az1 = 0, an0 = 0, an1 = 0;
#pragma unroll
            for (int i = 0; i < 32; i += 2) {
                ulonglong2 ha = *(const ulonglong2*)(hb + i * 32);
                ulonglong2 hc = *(const ulonglong2*)(hb + i * 32 + 32);
                ulonglong2 wr = *(const ulonglong2*)(wrp + i);
                ulonglong2 wz = *(const ulonglong2*)(wzp + i);
                ulonglong2 wn = *(const ulonglong2*)(wnp + i);
                ar0 = f2fma(ha.x, wr.x, ar0); ar1 = f2fma(ha.y, wr.x, ar1);
                ar0 = f2fma(hc.x, wr.y, ar0); ar1 = f2fma(hc.y, wr.y, ar1);
                az0 = f2fma(ha.x, wz.x, az0); az1 = f2fma(ha.y, wz.x, az1);
                az0 = f2fma(hc.x, wz.y, az0); az1 = f2fma(hc.y, wz.y, az1);
                an0 = f2fma(ha.x, wn.x, an0); an1 = f2fma(ha.y, wn.x, an1);
                an0 = f2fma(hc.x, wn.y, an0); an1 = f2fma(hc.y, wn.y, an1);
            }
            {
                u64* rb = redA + (size_t)kq * 384 + (j * 8 + bq) * 2;
                *(ulonglong2*)(rb)       = make_ulonglong2(ar0, ar1);
                *(ulonglong2*)(rb + 128) = make_ulonglong2(az0, az1);
                *(ulonglong2*)(rb + 256) = make_ulonglong2(an0, an1);
            }
            BARA();

            if (a < 192) {
                u64 s0 = 0, s1 = 0;
                const u64* base = redA + a * 2;
#pragma unroll
                for (int q = 0; q < 8; q++) {
                    ulonglong2 v = *(const ulonglong2*)(base + q * 384);
                    s0 = f2add(s0, v.x);
                    s1 = f2add(s1, v.y);
                }
                int g = a >> 6, jj = (a >> 3) & 7, bb = a & 7;
                float l0, h0f, l1, h1f;
                up2(s0, l0, h0f); up2(s1, l1, h1f);
                *(float4*)(red2A + (g * 8 + jj) * 32 + bb * 4) = make_float4(l0, h0f, l1, h1f);
            }
            BARA();

            if (a < 256) {
                float gr = red2A[aj * 32 + ab]        + bhA[aj];
                float gz = red2A[(8 + aj) * 32 + ab]  + bhA[8 + aj];
                float gn = red2A[(16 + aj) * 32 + ab] + bhA[16 + aj];
                float r = 1.0f / (1.0f + __expf(-(cir + gr)));
                float z = 1.0f / (1.0f + __expf(-(ciz + gz)));
                float n = tanhf(cin_ + r * gn);
                float hprev = h_sA[(j0 + aj) * 32 + ab];
                float hnew = (1.0f - z) * n + z * hprev;
                g_hseq0[(size_t)t * 32768 + (size_t)(j0 + aj) * Bsz + b0 + ab] = hnew;
            }
            BARA();

            if (a == 0) {
                asm volatile("st.release.gpu.u32 [%0], %1;"
                             :: "l"(myflagA), "r"((unsigned)(t + 1)) : "memory");
            }
            if (a < 256 && t + 1 < Lseq) {
                const float* gi_n = g_gi + (size_t)(t + 1) * (G3 * Bsz);
                cir  = __ldg(gi_n + gidx);
                ciz  = __ldg(gi_n + 32768 + gidx);
                cin_ = __ldg(gi_n + 65536 + gidx);
            }
        }
    } else {
        // ================= B team: layer 1 (gi1 + gh1 in-loop) =================
        const int bti = tid - 512;
        const int bq = bti & 7;
        const int j  = (bti >> 3) & 7;
        const int kq = bti >> 6;
        const int kbase = kq * 32;

        const float* wj = wB + j * 260;   // + M*2080 + k, M in 0..5

        const int ab = bti & 31;
        const int aj = (bti >> 5) & 7;

        for (int t = 0; t < Lseq; t++) {
            // wait for h0(t) chunks (this thread's 4) and h1(t-1) chunks
#pragma unroll
            for (int e = 0; e < 4; e++) {
                const unsigned* fp = &g_flagA[(bt * 32 + kq * 4 + e) * 32];
                unsigned v;
                do {
                    asm volatile("ld.acquire.gpu.u32 %0, [%1];" : "=r"(v) : "l"(fp) : "memory");
                } while (v < (unsigned)(t + 1));
            }
            if (t > 0) {
#pragma unroll
                for (int e = 0; e < 4; e++) {
                    const unsigned* fp = &g_flagB[(bt * 32 + kq * 4 + e) * 32];
                    unsigned v;
                    do {
                        asm volatile("ld.acquire.gpu.u32 %0, [%1];" : "=r"(v) : "l"(fp) : "memory");
                    } while (v < (unsigned)t);
                }
            }

            const float* h0p = g_hseq0 + (size_t)t * 32768 + b0 + bq * 4;
            const float* h1p = (t ? g_hseq1 + (size_t)(t - 1) * 32768 : g_h1init) + b0 + bq * 4;

            u64 acc[12];
#pragma unroll
            for (int m = 0; m < 12; m++) acc[m] = 0ull;

#pragma unroll 4
            for (int i = 0; i < 32; i += 2) {
                int k = kbase + i;
                float4 h0a = *(const float4*)(h0p + (size_t)k * 128);
                float4 h0b = *(const float4*)(h0p + (size_t)(k + 1) * 128);
                float4 h1a = *(const float4*)(h1p + (size_t)k * 128);
                float4 h1b = *(const float4*)(h1p + (size_t)(k + 1) * 128);
                const u64* H0a = (const u64*)&h0a;
                const u64* H0b = (const u64*)&h0b;
                const u64* H1a = (const u64*)&h1a;
                const u64* H1b = (const u64*)&h1b;
#pragma unroll
                for (int m = 0; m < 3; m++) {
                    float2 wi = *(const float2*)(wj + m * 2080 + k);
                    u64 w0 = dup2(wi.x), w1 = dup2(wi.y);
                    acc[2 * m]     = f2fma(H0a[0], w0, acc[2 * m]);
                    acc[2 * m + 1] = f2fma(H0a[1], w0, acc[2 * m + 1]);
                    acc[2 * m]     = f2fma(H0b[0], w1, acc[2 * m]);
                    acc[2 * m + 1] = f2fma(H0b[1], w1, acc[2 * m + 1]);
                    float2 wh = *(const float2*)(wj + (3 + m) * 2080 + k);
                    u64 v0 = dup2(wh.x), v1 = dup2(wh.y);
                    acc[6 + 2 * m]     = f2fma(H1a[0], v0, acc[6 + 2 * m]);
                    acc[6 + 2 * m + 1] = f2fma(H1a[1], v0, acc[6 + 2 * m + 1]);
                    acc[6 + 2 * m]     = f2fma(H1b[0], v1, acc[6 + 2 * m]);
                    acc[6 + 2 * m + 1] = f2fma(H1b[1], v1, acc[6 + 2 * m + 1]);
                }
            }
#pragma unroll
            for (int M = 0; M < 6; M++) {
                *(ulonglong2*)(redB + (size_t)kq * 768 + M * 128 + (j * 8 + bq) * 2) =
                    make_ulonglong2(acc[2 * M], acc[2 * M + 1]);
            }
            BARB();

            if (bti < 384) {
                int M = bti >> 6, jj = (bti >> 3) & 7, bb = bti & 7;
                const u64* base = redB + M * 128 + (jj * 8 + bb) * 2;
                u64 s0 = 0, s1 = 0;
#pragma unroll
                for (int q = 0; q < 8; q++) {
                    ulonglong2 v = *(const ulonglong2*)(base + q * 768);
                    s0 = f2add(s0, v.x);
                    s1 = f2add(s1, v.y);
                }
                float l0, h0f, l1, h1f;
                up2(s0, l0, h0f); up2(s1, l1, h1f);
                *(float4*)(red2B + (M * 8 + jj) * 32 + bb * 4) = make_float4(l0, h0f, l1, h1f);
            }
            BARB();

            if (bti < 256) {
                float gir = red2B[(0 * 8 + aj) * 32 + ab];
                float giz = red2B[(1 * 8 + aj) * 32 + ab];
                float gin = red2B[(2 * 8 + aj) * 32 + ab];
                float ghr = red2B[(3 * 8 + aj) * 32 + ab];
                float ghz = red2B[(4 * 8 + aj) * 32 + ab];
                float ghn = red2B[(5 * 8 + aj) * 32 + ab];
                float r = 1.0f / (1.0f + __expf(-(gir + ghr + bhB[aj])));
                float z = 1.0f / (1.0f + __expf(-(giz + ghz + bhB[8 + aj])));
                float n = tanhf(gin + bhB[16 + aj] + r * (ghn + bhB[24 + aj]));
                const float* hpp = (t ? g_hseq1 + (size_t)(t - 1) * 32768 : g_h1init);
                float hprev = hpp[(size_t)(j0 + aj) * 128 + b0 + ab];
                float hnew = (1.0f - z) * n + z * hprev;
                g_hseq1[(size_t)t * 32768 + (size_t)(j0 + aj) * 128 + b0 + ab] = hnew;
            }
            BARB();

            if (bti == 0) {
                asm volatile("st.release.gpu.u32 [%0], %1;"
                             :: "l"(myflagB), "r"((unsigned)(t + 1)) : "memory");
            }
        }
    }
}

// ---------------- transpose g_hseq1 [t][h][b] -> out [b][t][h] ----------------
__global__ __launch_bounds__(256) void transpose_out_kernel(float* __restrict__ out)
{
    __shared__ float tile[32 * 129];
    const int t  = blockIdx.y;
    const int h0 = blockIdx.x * 32;
    const int tid = threadIdx.x;
    const float* src = g_hseq1 + (size_t)t * (Hd * Bsz) + (size_t)h0 * Bsz;

    for (int idx = tid; idx < 4096; idx += 256) {
        int hh = idx >> 7, bb = idx & 127;
        tile[hh * 129 + bb] = src[idx];
    }
    __syncthreads();
    for (int idx = tid; idx < 4096; idx += 256) {
        int bb = idx >> 5, hh = idx & 31;
        out[(size_t)bb * Lseq * Hd + (size_t)t * Hd + h0 + hh] = tile[hh * 129 + bb];
    }
}

// ---------------- final hidden states ----------------
__global__ __launch_bounds__(256) void hn_kernel(float* __restrict__ out)
{
    int idx = blockIdx.x * blockDim.x + threadIdx.x;  // 0..65535
    int layer = idx >> 15;
    int b = (idx >> 8) & 127;
    int h = idx & 255;
    const float* hs = layer ? g_hseq1 : g_hseq0;
    out[(size_t)Bsz * Lseq * Hd + idx] =
        hs[(size_t)(Lseq - 1) * (Hd * Bsz) + (size_t)h * Bsz + b];
}

// ---------------- launcher ----------------
extern "C" void kernel_launch(void* const* d_in, const int* in_sizes, int n_in,
                              void* d_out, int out_size)
{
    const float* x     = (const float*)d_in[0];
    const float* h0    = (const float*)d_in[1];
    const float* w_ih0 = (const float*)d_in[2];
    const float* w_hh0 = (const float*)d_in[3];
    const float* b_ih0 = (const float*)d_in[4];
    const float* b_hh0 = (const float*)d_in[5];
    const float* w_ih1 = (const float*)d_in[6];
    const float* w_hh1 = (const float*)d_in[7];
    const float* b_ih1 = (const float*)d_in[8];
    const float* b_hh1 = (const float*)d_in[9];
    float* out = (float*)d_out;

    const size_t smem = (size_t)(6192 + 3072 + 6144) * sizeof(u64)
                      + (size_t)(12480 + 8192 + 768 + 1536 + 32 + 32) * sizeof(float)
                      + 32 * sizeof(unsigned);   // 215,552 B
    cudaFuncSetAttribute(gru_fused_kernel,
                         cudaFuncAttributeMaxDynamicSharedMemorySize, (int)smem);

    gi_gemm_kernel<<<dim3(6, Lseq), 256>>>(x, w_ih0, b_ih0);
    gru_fused_kernel<<<FBLK, 1024, smem>>>(w_hh0, b_hh0, w_ih1, w_hh1, b_ih1, b_hh1, h0);
    transpose_out_kernel<<<dim3(8, Lseq), 256>>>(out);
    if (out_size >= (int)((size_t)Bsz * Lseq * Hd + 2 * Bsz * Hd))
        hn_kernel<<<256, 256>>>(out);
}

// round 13
// speedup vs baseline: 1.1741x; 1.1741x over previous
#include <cuda_runtime.h>
#include <cstdint>

#define Bsz 128
#define Lseq 1024
#define Hd 256
#define G3 768
#define W2S 258   // u64 stride per duplicated-weight row

typedef unsigned long long u64;

__device__ __forceinline__ u64 f2fma(u64 a, u64 b, u64 c) {
    u64 d; asm("fma.rn.f32x2 %0, %1, %2, %3;" : "=l"(d) : "l"(a), "l"(b), "l"(c)); return d;
}
__device__ __forceinline__ u64 f2add(u64 a, u64 b) {
    u64 d; asm("add.rn.f32x2 %0, %1, %2;" : "=l"(d) : "l"(a), "l"(b)); return d;
}
__device__ __forceinline__ u64 dup2(float x) {
    u64 r; asm("mov.b64 %0, {%1, %1};" : "=l"(r) : "f"(x)); return r;
}
__device__ __forceinline__ void up2(u64 v, float& lo, float& hi) {
    asm("mov.b64 {%0, %1}, %2;" : "=f"(lo), "=f"(hi) : "l"(v));
}

// ---------------- scratch ----------------
__device__ float g_gi[(size_t)Lseq * G3 * Bsz];      // [t][3H][B]
__device__ float g_hseq0[(size_t)Lseq * Hd * Bsz];   // [t][k][b]
__device__ float g_hseq1[(size_t)Lseq * Hd * Bsz];

__device__ unsigned g_flagA[4 * 32 * 32];   // layer-0 progress flags (monotonic)
__device__ unsigned g_flagB[4 * 32 * 32];   // layer-1 progress flags (monotonic)
__device__ unsigned g_epoch = 0;

__global__ void epoch_kernel() {
    if (threadIdx.x == 0 && blockIdx.x == 0) g_epoch = g_epoch + 1u;
}

// ---------------- input-side GEMM (layer 0): Gi[t][c][b] ----------------
__global__ __launch_bounds__(256) void gi_gemm_kernel(
    const float* __restrict__ xin, const float* __restrict__ W,
    const float* __restrict__ bias)
{
    __shared__ float Ws[16 * 132];
    __shared__ float As[16 * 132];

    const int t  = blockIdx.y;
    const int c0 = blockIdx.x * 128;
    const int tid = threadIdx.x;
    const int ty = tid >> 4;
    const int tx = tid & 15;

    u64 acc2[8][4];
#pragma unroll
    for (int i = 0; i < 8; i++)
#pragma unroll
        for (int j = 0; j < 4; j++) acc2[i][j] = 0ull;

    for (int k0 = 0; k0 < 256; k0 += 16) {
        {
            int row  = tid >> 2;
            int col4 = (tid & 3) * 4;
#pragma unroll
            for (int it = 0; it < 2; it++, row += 64) {
                float4 w = *(const float4*)(W + (size_t)(c0 + row) * 256 + k0 + col4);
                Ws[(col4 + 0) * 132 + row] = w.x;
                Ws[(col4 + 1) * 132 + row] = w.y;
                Ws[(col4 + 2) * 132 + row] = w.z;
                Ws[(col4 + 3) * 132 + row] = w.w;
            }
        }
        {
            int row  = tid >> 2;
            int col4 = (tid & 3) * 4;
#pragma unroll
            for (int it = 0; it < 2; it++, row += 64) {
                float4 a = *(const float4*)(xin + ((size_t)row * Lseq + t) * 256 + k0 + col4);
                As[(col4 + 0) * 132 + row] = a.x;
                As[(col4 + 1) * 132 + row] = a.y;
                As[(col4 + 2) * 132 + row] = a.z;
                As[(col4 + 3) * 132 + row] = a.w;
            }
        }
        __syncthreads();

#pragma unroll
        for (int kk = 0; kk < 16; kk++) {
            float wr[8];
            *(float4*)(wr)     = *(const float4*)(Ws + kk * 132 + ty * 4);
            *(float4*)(wr + 4) = *(const float4*)(Ws + kk * 132 + 64 + ty * 4);
            ulonglong2 aA = *(const ulonglong2*)(As + kk * 132 + tx * 4);
            ulonglong2 aB = *(const ulonglong2*)(As + kk * 132 + 64 + tx * 4);
#pragma unroll
            for (int i = 0; i < 8; i++) {
                u64 wd = dup2(wr[i]);
                acc2[i][0] = f2fma(aA.x, wd, acc2[i][0]);
                acc2[i][1] = f2fma(aA.y, wd, acc2[i][1]);
                acc2[i][2] = f2fma(aB.x, wd, acc2[i][2]);
                acc2[i][3] = f2fma(aB.y, wd, acc2[i][3]);
            }
        }
        __syncthreads();
    }

    float* gout = g_gi + (size_t)t * G3 * Bsz;
#pragma unroll
    for (int i = 0; i < 8; i++) {
        int c = (i < 4) ? (c0 + ty * 4 + i) : (c0 + 64 + ty * 4 + (i - 4));
        float bv = bias[c];
        float a0, a1, a2, a3, a4, a5, a6, a7;
        up2(acc2[i][0], a0, a1); up2(acc2[i][1], a2, a3);
        up2(acc2[i][2], a4, a5); up2(acc2[i][3], a6, a7);
        *(float4*)(gout + (size_t)c * Bsz + tx * 4) =
            make_float4(a0 + bv, a1 + bv, a2 + bv, a3 + bv);
        *(float4*)(gout + (size_t)c * Bsz + 64 + tx * 4) =
            make_float4(a4 + bv, a5 + bv, a6 + bv, a7 + bv);
    }
}

// ---------------- persistent GRU recurrence + scavenger gemm ----------------
// bids 0-127: recurrence (R11 dataflow shape, merged reduce+act).
// bids >= 128 (layer-0 launch only): scavenger blocks computing layer-1 input
// gates gi1[t] = W_ih1 . h0(t), polling layer-0's h flags per timestep.
__global__ __launch_bounds__(512, 2) void gru_recur_kernel(
    const float* __restrict__ w_hh, const float* __restrict__ b_hh,
    const float* __restrict__ h0all, int layer,
    const float* __restrict__ w_sc, const float* __restrict__ b_sc)
{
    extern __shared__ __align__(16) char smraw[];
    const int tid = threadIdx.x;
    const unsigned FB = (*(volatile unsigned*)&g_epoch) * 2048u;

    if (blockIdx.x >= 128) {
        // ================= scavenger: gi1 tiles (64c x 128b x 4t) =================
        float* Ws = (float*)smraw;        // 16k x 64c, stride 68
        float* As = Ws + 16 * 68;         // 16k x 128b, stride 132
        const int g  = blockIdx.x - 128;
        const int ct = g % 12;
        const int tb = g / 12;
        const int c0s = ct * 64;
        const int ty = (tid & 255) >> 4;
        const int tx = tid & 15;

        for (int tt = 0; tt < 4; tt++) {
            const int t = tb * 4 + tt;
            if (tid < 128) {
                const unsigned* fp = &g_flagA[tid * 32];
                unsigned v;
                for (;;) {
                    asm volatile("ld.acquire.gpu.u32 %0, [%1];" : "=r"(v) : "l"(fp) : "memory");
                    if (v >= FB + (unsigned)(t + 1)) break;
                    __nanosleep(2000);
                }
            }
            __syncthreads();

            u64 acc2[4][4];
#pragma unroll
            for (int i = 0; i < 4; i++)
#pragma unroll
                for (int q = 0; q < 4; q++) acc2[i][q] = 0ull;

            const float* hsrc = g_hseq0 + (size_t)t * (Hd * Bsz);
            for (int k0 = 0; k0 < 256; k0 += 16) {
                for (int i = tid; i < 1024; i += 512) {
                    int row = i >> 4, kk = i & 15;
                    Ws[kk * 68 + row] = w_sc[(size_t)(c0s + row) * 256 + k0 + kk];
                }
                for (int i = tid; i < 2048; i += 512) {
                    int k = i >> 7, b = i & 127;
                    As[k * 132 + b] = hsrc[(size_t)(k0 + k) * 128 + b];
                }
                __syncthreads();
                if (tid < 256) {
#pragma unroll
                    for (int kk = 0; kk < 16; kk++) {
                        float wr[4];
                        wr[0] = Ws[kk * 68 + ty * 4 + 0];
                        wr[1] = Ws[kk * 68 + ty * 4 + 1];
                        wr[2] = Ws[kk * 68 + ty * 4 + 2];
                        wr[3] = Ws[kk * 68 + ty * 4 + 3];
                        ulonglong2 aA = *(const ulonglong2*)(As + kk * 132 + tx * 4);
                        ulonglong2 aB = *(const ulonglong2*)(As + kk * 132 + 64 + tx * 4);
#pragma unroll
                        for (int i = 0; i < 4; i++) {
                            u64 wd = dup2(wr[i]);
                            acc2[i][0] = f2fma(aA.x, wd, acc2[i][0]);
                            acc2[i][1] = f2fma(aA.y, wd, acc2[i][1]);
                            acc2[i][2] = f2fma(aB.x, wd, acc2[i][2]);
                            acc2[i][3] = f2fma(aB.y, wd, acc2[i][3]);
                        }
                    }
                }
                __syncthreads();
            }
            if (tid < 256) {
                float* gout = g_gi + (size_t)t * (G3 * Bsz);
#pragma unroll
                for (int i = 0; i < 4; i++) {
                    int c = c0s + ty * 4 + i;
                    float bv = b_sc[c];
                    float a0, a1, a2, a3, a4, a5, a6, a7;
                    up2(acc2[i][0], a0, a1); up2(acc2[i][1], a2, a3);
                    up2(acc2[i][2], a4, a5); up2(acc2[i][3], a6, a7);
                    *(float4*)(gout + (size_t)c * Bsz + tx * 4) =
                        make_float4(a0 + bv, a1 + bv, a2 + bv, a3 + bv);
                    *(float4*)(gout + (size_t)c * Bsz + 64 + tx * 4) =
                        make_float4(a4 + bv, a5 + bv, a6 + bv, a7 + bv);
                }
            }
            __syncthreads();
        }
        return;
    }

    // ================= recurrence (R11 shape, merged reduce+act) =================
    u64*   w2_s  = (u64*)smraw;            // 24*258 = 6192 u64
    u64*   red_s = w2_s + 6192;            // 8 kq * 384 = 3072 u64
    float* h_s   = (float*)(red_s + 3072); // 256 k * 32 b = 8192 floats
    float* bh_s  = h_s + 8192;             // 24 floats (+pad to 32)
    volatile unsigned* smflag = (volatile unsigned*)(bh_s + 32);  // 32 chunk flags

    const int bt = blockIdx.x >> 5;
    const int ht = blockIdx.x & 31;
    const int b0 = bt * 32;
    const int j0 = ht * 8;

    float* hseq = layer ? g_hseq1 : g_hseq0;
    unsigned* flags = layer ? g_flagB : g_flagA;
    unsigned* myflag = &flags[(bt * 32 + ht) * 32];

    if (tid < 32) smflag[tid] = 0u;

    // duplicated persistent weights
    for (int idx = tid; idx < 6144; idx += 512) {
        int gj = idx >> 8;
        int k  = idx & 255;
        int g  = gj >> 3, j = gj & 7;
        w2_s[gj * W2S + k] = dup2(__ldg(w_hh + (size_t)(g * 256 + j0 + j) * 256 + k));
    }
    if (tid < 24) {
        int g = tid >> 3, j = tid & 7;
        bh_s[tid] = b_hh[g * 256 + j0 + j];
    }
    __syncthreads();

    const int bq = tid & 7;
    const int j  = (tid >> 3) & 7;
    const int kq = tid >> 6;
    const int kbase = kq * 32;
    const int warp = tid >> 5;
    const int lane = tid & 31;

    const u64* wrp = w2_s + (0 + j) * W2S + kbase;
    const u64* wzp = w2_s + (8 + j) * W2S + kbase;
    const u64* wnp = w2_s + (16 + j) * W2S + kbase;
    const float* hb = h_s + kbase * 32 + bq * 4;

    // merged reduce+act mapping (tid < 128): aj = hidden unit, bp = batch pair
    const int aj = tid >> 4;
    const int bp = tid & 15;
    const size_t gidx2 = (size_t)(j0 + aj) * Bsz + b0 + 2 * bp;

    float2 cir2 = make_float2(0.f, 0.f), ciz2 = cir2, cin2 = cir2;
    if (tid < 128) {
        cir2 = *(const float2*)(g_gi + gidx2);
        ciz2 = *(const float2*)(g_gi + 32768 + gidx2);
        cin2 = *(const float2*)(g_gi + 65536 + gidx2);
    }

    for (int t = 0; t < Lseq; t++) {
        // ---- stage h(t-1) ----
        if (t == 0) {
            const float* h0g = h0all + (size_t)layer * Bsz * Hd;  // [b][k]
            for (int i = tid; i < 8192; i += 512) {
                int k = i >> 5, bb = i & 31;
                h_s[k * 32 + bb] = h0g[(size_t)(b0 + bb) * 256 + k];
            }
            __syncthreads();
        } else {
            const float* src = hseq + (size_t)(t - 1) * (Hd * Bsz);
            const int kq_w = warp >> 1;
#pragma unroll
            for (int e = 0; e < 2; e++) {
                int c = kq_w * 4 + (warp & 1) * 2 + e;
                const unsigned* fp = &flags[(bt * 32 + c) * 32];
                unsigned v;
                do {
                    asm volatile("ld.acquire.gpu.u32 %0, [%1];" : "=r"(v) : "l"(fp) : "memory");
                } while (v < FB + (unsigned)t);
                int k   = c * 8 + (lane >> 2);
                int col = (lane & 3) * 4;
                const float* sp = src + (size_t)k * Bsz + b0;
                float4 v0 = *(const float4*)(sp + col);
                float4 v1 = *(const float4*)(sp + col + 16);
                *(float4*)(h_s + k * 32 + col)      = v0;
                *(float4*)(h_s + k * 32 + col + 16) = v1;
                __syncwarp();
                __threadfence_block();
                if (lane == 0) smflag[c] = (unsigned)t;
            }
#pragma unroll
            for (int e = 0; e < 4; e++) {
                int c = kq * 4 + e;
                while (smflag[c] < (unsigned)t) { }
            }
            __threadfence_block();
        }

        // ---- partial dot over this thread's 32 k (f32x2 over batch) ----
        u64 ar0 = 0, ar1 = 0, az0 = 0, az1 = 0, an0 = 0, an1 = 0;
#pragma unroll
        for (int i = 0; i < 32; i += 2) {
            ulonglong2 ha = *(const ulonglong2*)(hb + i * 32);
            ulonglong2 hc = *(const ulonglong2*)(hb + i * 32 + 32);
            ulonglong2 wr = *(const ulonglong2*)(wrp + i);
            ulonglong2 wz = *(const ulonglong2*)(wzp + i);
            ulonglong2 wn = *(const ulonglong2*)(wnp + i);
            ar0 = f2fma(ha.x, wr.x, ar0); ar1 = f2fma(ha.y, wr.x, ar1);
            ar0 = f2fma(hc.x, wr.y, ar0); ar1 = f2fma(hc.y, wr.y, ar1);
            az0 = f2fma(ha.x, wz.x, az0); az1 = f2fma(ha.y, wz.x, az1);
            az0 = f2fma(hc.x, wz.y, az0); az1 = f2fma(hc.y, wz.y, az1);
            an0 = f2fma(ha.x, wn.x, an0); an1 = f2fma(ha.y, wn.x, an1);
            an0 = f2fma(hc.x, wn.y, an0); an1 = f2fma(hc.y, wn.y, an1);
        }
        {
            u64* rb = red_s + (size_t)kq * 384 + (j * 8 + bq) * 2;
            *(ulonglong2*)(rb)       = make_ulonglong2(ar0, ar1);
            *(ulonglong2*)(rb + 128) = make_ulonglong2(az0, az1);
            *(ulonglong2*)(rb + 256) = make_ulonglong2(an0, an1);
        }
        __syncthreads();

        // ---- merged reduce + activation (128 threads: 8 j x 16 b-pairs) ----
        if (tid < 128) {
            const u64* base = red_s + aj * 16 + bp;
            u64 sr = 0, sz = 0, sn = 0;
#pragma unroll
            for (int q = 0; q < 8; q++) {
                sr = f2add(sr, base[q * 384]);
                sz = f2add(sz, base[q * 384 + 128]);
                sn = f2add(sn, base[q * 384 + 256]);
            }
            float gr0, gr1, gz0, gz1, gn0, gn1;
            up2(sr, gr0, gr1); up2(sz, gz0, gz1); up2(sn, gn0, gn1);
            float bhr = bh_s[aj], bhz = bh_s[8 + aj], bhn = bh_s[16 + aj];

            float2 hp = *(const float2*)(h_s + (j0 + aj) * 32 + 2 * bp);

            float r0 = 1.0f / (1.0f + __expf(-(cir2.x + gr0 + bhr)));
            float r1 = 1.0f / (1.0f + __expf(-(cir2.y + gr1 + bhr)));
            float z0 = 1.0f / (1.0f + __expf(-(ciz2.x + gz0 + bhz)));
            float z1 = 1.0f / (1.0f + __expf(-(ciz2.y + gz1 + bhz)));
            float n0 = tanhf(cin2.x + r0 * (gn0 + bhn));
            float n1 = tanhf(cin2.y + r1 * (gn1 + bhn));
            float hn0 = (1.0f - z0) * n0 + z0 * hp.x;
            float hn1 = (1.0f - z1) * n1 + z1 * hp.y;

            *(float2*)(hseq + (size_t)t * (Hd * Bsz) + gidx2) = make_float2(hn0, hn1);
        }
        __syncthreads();

        if (tid == 0) {
            asm volatile("st.release.gpu.u32 [%0], %1;"
                         :: "l"(myflag), "r"(FB + (unsigned)(t + 1)) : "memory");
        }
        if (tid < 128 && t + 1 < Lseq) {
            const float* gi_n = g_gi + (size_t)(t + 1) * (G3 * Bsz);
            cir2 = *(const float2*)(gi_n + gidx2);
            ciz2 = *(const float2*)(gi_n + 32768 + gidx2);
            cin2 = *(const float2*)(gi_n + 65536 + gidx2);
        }
    }
}

// ---------------- transpose g_hseq1 [t][h][b] -> out [b][t][h] ----------------
__global__ __launch_bounds__(256) void transpose_out_kernel(float* __restrict__ out)
{
    __shared__ float tile[32 * 129];
    const int t  = blockIdx.y;
    const int h0 = blockIdx.x * 32;
    const int tid = threadIdx.x;
    const float* src = g_hseq1 + (size_t)t * (Hd * Bsz) + (size_t)h0 * Bsz;

    for (int idx = tid; idx < 4096; idx += 256) {
        int hh = idx >> 7, bb = idx & 127;
        tile[hh * 129 + bb] = src[idx];
    }
    __syncthreads();
    for (int idx = tid; idx < 4096; idx += 256) {
        int bb = idx >> 5, hh = idx & 31;
        out[(size_t)bb * Lseq * Hd + (size_t)t * Hd + h0 + hh] = tile[hh * 129 + bb];
    }
}

// ---------------- final hidden states ----------------
__global__ __launch_bounds__(256) void hn_kernel(float* __restrict__ out)
{
    int idx = blockIdx.x * blockDim.x + threadIdx.x;  // 0..65535
    int layer = idx >> 15;
    int b = (idx >> 8) & 127;
    int h = idx & 255;
    const float* hs = layer ? g_hseq1 : g_hseq0;
    out[(size_t)Bsz * Lseq * Hd + idx] =
        hs[(size_t)(Lseq - 1) * (Hd * Bsz) + (size_t)h * Bsz + b];
}

// ---------------- launcher ----------------
extern "C" void kernel_launch(void* const* d_in, const int* in_sizes, int n_in,
                              void* d_out, int out_size)
{
    const float* x     = (const float*)d_in[0];
    const float* h0    = (const float*)d_in[1];
    const float* w_ih0 = (const float*)d_in[2];
    const float* w_hh0 = (const float*)d_in[3];
    const float* b_ih0 = (const float*)d_in[4];
    const float* b_hh0 = (const float*)d_in[5];
    const float* w_ih1 = (const float*)d_in[6];
    const float* w_hh1 = (const float*)d_in[7];
    const float* b_ih1 = (const float*)d_in[8];
    const float* b_hh1 = (const float*)d_in[9];
    float* out = (float*)d_out;

    const size_t smem = (6192 + 3072) * sizeof(u64)
                      + (8192 + 32) * sizeof(float)
                      + 32 * sizeof(unsigned);   // 107,136 B
    cudaFuncSetAttribute(gru_recur_kernel,
                         cudaFuncAttributeMaxDynamicSharedMemorySize, (int)smem);

    epoch_kernel<<<1, 32>>>();
    gi_gemm_kernel<<<dim3(6, Lseq), 256>>>(x, w_ih0, b_ih0);
    // layer 0 + scavenger gemm1 (3072 tiles of 64c x 128b x 4t)
    gru_recur_kernel<<<128 + 3072, 512, smem>>>(w_hh0, b_hh0, h0, 0, w_ih1, b_ih1);
    // layer 1
    gru_recur_kernel<<<128, 512, smem>>>(w_hh1, b_hh1, h0, 1, w_ih1, b_ih1);
    transpose_out_kernel<<<dim3(8, Lseq), 256>>>(out);
    if (out_size >= (int)((size_t)Bsz * Lseq * Hd + 2 * Bsz * Hd))
        hn_kernel<<<256, 256>>>(out);
}

// round 14
// speedup vs baseline: 1.3996x; 1.1921x over previous
#include <cuda_runtime.h>
#include <cstdint>

#define Bsz 128
#define Lseq 1024
#define Hd 256
#define G3 768
#define W2S 258   // u64 stride per duplicated-weight row

typedef unsigned long long u64;

__device__ __forceinline__ u64 f2fma(u64 a, u64 b, u64 c) {
    u64 d; asm("fma.rn.f32x2 %0, %1, %2, %3;" : "=l"(d) : "l"(a), "l"(b), "l"(c)); return d;
}
__device__ __forceinline__ u64 f2add(u64 a, u64 b) {
    u64 d; asm("add.rn.f32x2 %0, %1, %2;" : "=l"(d) : "l"(a), "l"(b)); return d;
}
__device__ __forceinline__ u64 dup2(float x) {
    u64 r; asm("mov.b64 %0, {%1, %1};" : "=l"(r) : "f"(x)); return r;
}
__device__ __forceinline__ void up2(u64 v, float& lo, float& hi) {
    asm("mov.b64 {%0, %1}, %2;" : "=f"(lo), "=f"(hi) : "l"(v));
}

// ---------------- scratch ----------------
__device__ float g_gi[(size_t)Lseq * G3 * Bsz];      // layer-0 input gates [t][3H][B]
__device__ float g_gi1[(size_t)Lseq * G3 * Bsz];     // layer-1 input gates [t][3H][B]
__device__ float g_hseq0[(size_t)Lseq * Hd * Bsz];   // [t][k][b]
__device__ float g_hseq1[(size_t)Lseq * Hd * Bsz];

__device__ unsigned g_flagA[4 * 32 * 32];   // layer-0 h progress (monotonic)
__device__ unsigned g_flagB[4 * 32 * 32];   // layer-1 h progress (monotonic)
__device__ unsigned g_giflag[Lseq * 12];    // gi1 tile-ready flags (== epoch)
__device__ unsigned g_epoch = 0;

__global__ void epoch_kernel() {
    if (threadIdx.x == 0 && blockIdx.x == 0) g_epoch = g_epoch + 1u;
}

// ---------------- input-side GEMM (layer 0): Gi[t][c][b] ----------------
__global__ __launch_bounds__(256) void gi_gemm_kernel(
    const float* __restrict__ xin, const float* __restrict__ W,
    const float* __restrict__ bias)
{
    __shared__ float Ws[16 * 132];
    __shared__ float As[16 * 132];

    const int t  = blockIdx.y;
    const int c0 = blockIdx.x * 128;
    const int tid = threadIdx.x;
    const int ty = tid >> 4;
    const int tx = tid & 15;

    u64 acc2[8][4];
#pragma unroll
    for (int i = 0; i < 8; i++)
#pragma unroll
        for (int j = 0; j < 4; j++) acc2[i][j] = 0ull;

    for (int k0 = 0; k0 < 256; k0 += 16) {
        {
            int row  = tid >> 2;
            int col4 = (tid & 3) * 4;
#pragma unroll
            for (int it = 0; it < 2; it++, row += 64) {
                float4 w = *(const float4*)(W + (size_t)(c0 + row) * 256 + k0 + col4);
                Ws[(col4 + 0) * 132 + row] = w.x;
                Ws[(col4 + 1) * 132 + row] = w.y;
                Ws[(col4 + 2) * 132 + row] = w.z;
                Ws[(col4 + 3) * 132 + row] = w.w;
            }
        }
        {
            int row  = tid >> 2;
            int col4 = (tid & 3) * 4;
#pragma unroll
            for (int it = 0; it < 2; it++, row += 64) {
                float4 a = *(const float4*)(xin + ((size_t)row * Lseq + t) * 256 + k0 + col4);
                As[(col4 + 0) * 132 + row] = a.x;
                As[(col4 + 1) * 132 + row] = a.y;
                As[(col4 + 2) * 132 + row] = a.z;
                As[(col4 + 3) * 132 + row] = a.w;
            }
        }
        __syncthreads();

#pragma unroll
        for (int kk = 0; kk < 16; kk++) {
            float wr[8];
            *(float4*)(wr)     = *(const float4*)(Ws + kk * 132 + ty * 4);
            *(float4*)(wr + 4) = *(const float4*)(Ws + kk * 132 + 64 + ty * 4);
            ulonglong2 aA = *(const ulonglong2*)(As + kk * 132 + tx * 4);
            ulonglong2 aB = *(const ulonglong2*)(As + kk * 132 + 64 + tx * 4);
#pragma unroll
            for (int i = 0; i < 8; i++) {
                u64 wd = dup2(wr[i]);
                acc2[i][0] = f2fma(aA.x, wd, acc2[i][0]);
                acc2[i][1] = f2fma(aA.y, wd, acc2[i][1]);
                acc2[i][2] = f2fma(aB.x, wd, acc2[i][2]);
                acc2[i][3] = f2fma(aB.y, wd, acc2[i][3]);
            }
        }
        __syncthreads();
    }

    float* gout = g_gi + (size_t)t * G3 * Bsz;
#pragma unroll
    for (int i = 0; i < 8; i++) {
        int c = (i < 4) ? (c0 + ty * 4 + i) : (c0 + 64 + ty * 4 + (i - 4));
        float bv = bias[c];
        float a0, a1, a2, a3, a4, a5, a6, a7;
        up2(acc2[i][0], a0, a1); up2(acc2[i][1], a2, a3);
        up2(acc2[i][2], a4, a5); up2(acc2[i][3], a6, a7);
        *(float4*)(gout + (size_t)c * Bsz + tx * 4) =
            make_float4(a0 + bv, a1 + bv, a2 + bv, a3 + bv);
        *(float4*)(gout + (size_t)c * Bsz + 64 + tx * 4) =
            make_float4(a4 + bv, a5 + bv, a6 + bv, a7 + bv);
    }
}

// ---------------- mega kernel: recur0 || recur1 || gemm1 ----------------
// bids 0-127:   layer-0 recurrence (dataflow flags, merged reduce+act)
// bids 128-255: layer-1 recurrence (gi from g_gi1, gated by g_giflag)
// bids 256+:    gemm1 scavenger tiles (gi1 = W_ih1 . h0(t) + b_ih1)
__global__ __launch_bounds__(512, 2) void gru_mega_kernel(
    const float* __restrict__ w_hh0, const float* __restrict__ b_hh0,
    const float* __restrict__ w_hh1, const float* __restrict__ b_hh1,
    const float* __restrict__ w_ih1, const float* __restrict__ b_ih1,
    const float* __restrict__ h0all)
{
    extern __shared__ __align__(16) char smraw[];
    const int tid = threadIdx.x;
    const unsigned E  = *(volatile unsigned*)&g_epoch;
    const unsigned FB = E * 2048u;

    if (blockIdx.x >= 256) {
        // ============ scavenger: gi1 tiles (64c x 128b x 4t) ============
        float* Ws = (float*)smraw;        // 16k x 64c, stride 68
        float* As = Ws + 16 * 68;         // 16k x 128b, stride 132
        const int g  = (int)blockIdx.x - 256;
        const int ct = g % 12;
        const int tb = g / 12;
        const int c0s = ct * 64;
        const int ty = (tid & 255) >> 4;
        const int tx = tid & 15;

        for (int tt = 0; tt < 4; tt++) {
            const int t = tb * 4 + tt;
            if (tid < 128) {
                const unsigned* fp = &g_flagA[tid * 32];
                unsigned v;
                for (;;) {
                    asm volatile("ld.acquire.gpu.u32 %0, [%1];" : "=r"(v) : "l"(fp) : "memory");
                    if (v >= FB + (unsigned)(t + 1)) break;
                    __nanosleep(2000);
                }
            }
            __syncthreads();

            u64 acc2[4][4];
#pragma unroll
            for (int i = 0; i < 4; i++)
#pragma unroll
                for (int q = 0; q < 4; q++) acc2[i][q] = 0ull;

            const float* hsrc = g_hseq0 + (size_t)t * (Hd * Bsz);
            for (int k0 = 0; k0 < 256; k0 += 16) {
                for (int i = tid; i < 1024; i += 512) {
                    int row = i >> 4, kk = i & 15;
                    Ws[kk * 68 + row] = w_ih1[(size_t)(c0s + row) * 256 + k0 + kk];
                }
                for (int i = tid; i < 2048; i += 512) {
                    int k = i >> 7, b = i & 127;
                    As[k * 132 + b] = hsrc[(size_t)(k0 + k) * 128 + b];
                }
                __syncthreads();
                if (tid < 256) {
#pragma unroll
                    for (int kk = 0; kk < 16; kk++) {
                        float wr[4];
                        wr[0] = Ws[kk * 68 + ty * 4 + 0];
                        wr[1] = Ws[kk * 68 + ty * 4 + 1];
                        wr[2] = Ws[kk * 68 + ty * 4 + 2];
                        wr[3] = Ws[kk * 68 + ty * 4 + 3];
                        ulonglong2 aA = *(const ulonglong2*)(As + kk * 132 + tx * 4);
                        ulonglong2 aB = *(const ulonglong2*)(As + kk * 132 + 64 + tx * 4);
#pragma unroll
                        for (int i = 0; i < 4; i++) {
                            u64 wd = dup2(wr[i]);
                            acc2[i][0] = f2fma(aA.x, wd, acc2[i][0]);
                            acc2[i][1] = f2fma(aA.y, wd, acc2[i][1]);
                            acc2[i][2] = f2fma(aB.x, wd, acc2[i][2]);
                            acc2[i][3] = f2fma(aB.y, wd, acc2[i][3]);
                        }
                    }
                }
                __syncthreads();
            }
            if (tid < 256) {
                float* gout = g_gi1 + (size_t)t * (G3 * Bsz);
#pragma unroll
                for (int i = 0; i < 4; i++) {
                    int c = c0s + ty * 4 + i;
                    float bv = b_ih1[c];
                    float a0, a1, a2, a3, a4, a5, a6, a7;
                    up2(acc2[i][0], a0, a1); up2(acc2[i][1], a2, a3);
                    up2(acc2[i][2], a4, a5); up2(acc2[i][3], a6, a7);
                    *(float4*)(gout + (size_t)c * Bsz + tx * 4) =
                        make_float4(a0 + bv, a1 + bv, a2 + bv, a3 + bv);
                    *(float4*)(gout + (size_t)c * Bsz + 64 + tx * 4) =
                        make_float4(a4 + bv, a5 + bv, a6 + bv, a7 + bv);
                }
            }
            __syncthreads();
            if (tid == 0) {
                asm volatile("st.release.gpu.u32 [%0], %1;"
                             :: "l"(&g_giflag[t * 12 + ct]), "r"(E) : "memory");
            }
        }
        return;
    }

    // ============ recurrence (both layers) ============
    u64*   w2_s  = (u64*)smraw;            // 24*258 = 6192 u64
    u64*   red_s = w2_s + 6192;            // 8 kq * 384 = 3072 u64
    float* h_s   = (float*)(red_s + 3072); // 256 k * 32 b = 8192 floats
    float* bh_s  = h_s + 8192;             // 24 floats (+pad to 32)
    volatile unsigned* smflag = (volatile unsigned*)(bh_s + 32);  // 32 chunk flags

    const int layer = (int)blockIdx.x >> 7;
    const int bid7  = (int)blockIdx.x & 127;
    const int bt = bid7 >> 5;
    const int ht = bid7 & 31;
    const int b0 = bt * 32;
    const int j0 = ht * 8;

    const float* w_hh = layer ? w_hh1 : w_hh0;
    const float* b_hh = layer ? b_hh1 : b_hh0;
    float* hseq = layer ? g_hseq1 : g_hseq0;
    unsigned* flags = layer ? g_flagB : g_flagA;
    unsigned* myflag = &flags[(bt * 32 + ht) * 32];
    const float* gi_src = layer ? g_gi1 : g_gi;

    // gi-tile flags this block needs (layer 1 only)
    const int ct0 = j0 >> 6;

    if (tid < 32) smflag[tid] = 0u;

    // duplicated persistent weights
    for (int idx = tid; idx < 6144; idx += 512) {
        int gj = idx >> 8;
        int k  = idx & 255;
        int g  = gj >> 3, j = gj & 7;
        w2_s[gj * W2S + k] = dup2(__ldg(w_hh + (size_t)(g * 256 + j0 + j) * 256 + k));
    }
    if (tid < 24) {
        int g = tid >> 3, j = tid & 7;
        bh_s[tid] = b_hh[g * 256 + j0 + j];
    }
    __syncthreads();

    const int bq = tid & 7;
    const int j  = (tid >> 3) & 7;
    const int kq = tid >> 6;
    const int kbase = kq * 32;
    const int warp = tid >> 5;
    const int lane = tid & 31;

    const u64* wrp = w2_s + (0 + j) * W2S + kbase;
    const u64* wzp = w2_s + (8 + j) * W2S + kbase;
    const u64* wnp = w2_s + (16 + j) * W2S + kbase;
    const float* hb = h_s + kbase * 32 + bq * 4;

    // merged reduce+act mapping (tid < 128): aj = hidden unit, bp = batch pair
    const int aj = tid >> 4;
    const int bp = tid & 15;
    const size_t gidx2 = (size_t)(j0 + aj) * Bsz + b0 + 2 * bp;

    float2 cir2 = make_float2(0.f, 0.f), ciz2 = cir2, cin2 = cir2;
    if (tid < 128) {
        if (layer) {
            unsigned v;
#pragma unroll
            for (int e = 0; e < 3; e++) {
                const unsigned* fp = &g_giflag[0 * 12 + 4 * e + ct0];
                do {
                    asm volatile("ld.acquire.gpu.u32 %0, [%1];" : "=r"(v) : "l"(fp) : "memory");
                } while (v < E);
            }
        }
        cir2 = *(const float2*)(gi_src + gidx2);
        ciz2 = *(const float2*)(gi_src + 32768 + gidx2);
        cin2 = *(const float2*)(gi_src + 65536 + gidx2);
    }

    for (int t = 0; t < Lseq; t++) {
        // ---- stage h(t-1) ----
        if (t == 0) {
            const float* h0g = h0all + (size_t)layer * Bsz * Hd;  // [b][k]
            for (int i = tid; i < 8192; i += 512) {
                int k = i >> 5, bb = i & 31;
                h_s[k * 32 + bb] = h0g[(size_t)(b0 + bb) * 256 + k];
            }
            __syncthreads();
        } else {
            const float* src = hseq + (size_t)(t - 1) * (Hd * Bsz);
            const int kq_w = warp >> 1;
#pragma unroll
            for (int e = 0; e < 2; e++) {
                int c = kq_w * 4 + (warp & 1) * 2 + e;
                const unsigned* fp = &flags[(bt * 32 + c) * 32];
                unsigned v;
                do {
                    asm volatile("ld.acquire.gpu.u32 %0, [%1];" : "=r"(v) : "l"(fp) : "memory");
                } while (v < FB + (unsigned)t);
                int k   = c * 8 + (lane >> 2);
                int col = (lane & 3) * 4;
                const float* sp = src + (size_t)k * Bsz + b0;
                float4 v0 = *(const float4*)(sp + col);
                float4 v1 = *(const float4*)(sp + col + 16);
                *(float4*)(h_s + k * 32 + col)      = v0;
                *(float4*)(h_s + k * 32 + col + 16) = v1;
                __syncwarp();
                __threadfence_block();
                if (lane == 0) smflag[c] = (unsigned)t;
            }
#pragma unroll
            for (int e = 0; e < 4; e++) {
                int c = kq * 4 + e;
                while (smflag[c] < (unsigned)t) { }
            }
            __threadfence_block();
        }

        // ---- partial dot over this thread's 32 k (f32x2 over batch) ----
        u64 ar0 = 0, ar1 = 0, az0 = 0, az1 = 0, an0 = 0, an1 = 0;
#pragma unroll
        for (int i = 0; i < 32; i += 2) {
            ulonglong2 ha = *(const ulonglong2*)(hb + i * 32);
            ulonglong2 hc = *(const ulonglong2*)(hb + i * 32 + 32);
            ulonglong2 wr = *(const ulonglong2*)(wrp + i);
            ulonglong2 wz = *(const ulonglong2*)(wzp + i);
            ulonglong2 wn = *(const ulonglong2*)(wnp + i);
            ar0 = f2fma(ha.x, wr.x, ar0); ar1 = f2fma(ha.y, wr.x, ar1);
            ar0 = f2fma(hc.x, wr.y, ar0); ar1 = f2fma(hc.y, wr.y, ar1);
            az0 = f2fma(ha.x, wz.x, az0); az1 = f2fma(ha.y, wz.x, az1);
            az0 = f2fma(hc.x, wz.y, az0); az1 = f2fma(hc.y, wz.y, az1);
            an0 = f2fma(ha.x, wn.x, an0); an1 = f2fma(ha.y, wn.x, an1);
            an0 = f2fma(hc.x, wn.y, an0); an1 = f2fma(hc.y, wn.y, an1);
        }
        {
            u64* rb = red_s + (size_t)kq * 384 + (j * 8 + bq) * 2;
            *(ulonglong2*)(rb)       = make_ulonglong2(ar0, ar1);
            *(ulonglong2*)(rb + 128) = make_ulonglong2(az0, az1);
            *(ulonglong2*)(rb + 256) = make_ulonglong2(an0, an1);
        }
        __syncthreads();

        // ---- merged reduce + activation (128 threads: 8 j x 16 b-pairs) ----
        if (tid < 128) {
            const u64* base = red_s + aj * 16 + bp;
            u64 sr = 0, sz = 0, sn = 0;
#pragma unroll
            for (int q = 0; q < 8; q++) {
                sr = f2add(sr, base[q * 384]);
                sz = f2add(sz, base[q * 384 + 128]);
                sn = f2add(sn, base[q * 384 + 256]);
            }
            float gr0, gr1, gz0, gz1, gn0, gn1;
            up2(sr, gr0, gr1); up2(sz, gz0, gz1); up2(sn, gn0, gn1);
            float bhr = bh_s[aj], bhz = bh_s[8 + aj], bhn = bh_s[16 + aj];

            float2 hp = *(const float2*)(h_s + (j0 + aj) * 32 + 2 * bp);

            float r0 = 1.0f / (1.0f + __expf(-(cir2.x + gr0 + bhr)));
            float r1 = 1.0f / (1.0f + __expf(-(cir2.y + gr1 + bhr)));
            float z0 = 1.0f / (1.0f + __expf(-(ciz2.x + gz0 + bhz)));
            float z1 = 1.0f / (1.0f + __expf(-(ciz2.y + gz1 + bhz)));
            float n0 = tanhf(cin2.x + r0 * (gn0 + bhn));
            float n1 = tanhf(cin2.y + r1 * (gn1 + bhn));
            float hn0 = (1.0f - z0) * n0 + z0 * hp.x;
            float hn1 = (1.0f - z1) * n1 + z1 * hp.y;

            *(float2*)(hseq + (size_t)t * (Hd * Bsz) + gidx2) = make_float2(hn0, hn1);
        }
        __syncthreads();

        if (tid == 0) {
            asm volatile("st.release.gpu.u32 [%0], %1;"
                         :: "l"(myflag), "r"(FB + (unsigned)(t + 1)) : "memory");
        }
        if (tid < 128 && t + 1 < Lseq) {
            if (layer) {
                unsigned v;
#pragma unroll
                for (int e = 0; e < 3; e++) {
                    const unsigned* fp = &g_giflag[(t + 1) * 12 + 4 * e + ct0];
                    do {
                        asm volatile("ld.acquire.gpu.u32 %0, [%1];" : "=r"(v) : "l"(fp) : "memory");
                    } while (v < E);
                }
            }
            const float* gi_n = gi_src + (size_t)(t + 1) * (G3 * Bsz);
            cir2 = *(const float2*)(gi_n + gidx2);
            ciz2 = *(const float2*)(gi_n + 32768 + gidx2);
            cin2 = *(const float2*)(gi_n + 65536 + gidx2);
        }
    }
}

// ---------------- transpose g_hseq1 [t][h][b] -> out [b][t][h] ----------------
__global__ __launch_bounds__(256) void transpose_out_kernel(float* __restrict__ out)
{
    __shared__ float tile[32 * 129];
    const int t  = blockIdx.y;
    const int h0 = blockIdx.x * 32;
    const int tid = threadIdx.x;
    const float* src = g_hseq1 + (size_t)t * (Hd * Bsz) + (size_t)h0 * Bsz;

    for (int idx = tid; idx < 4096; idx += 256) {
        int hh = idx >> 7, bb = idx & 127;
        tile[hh * 129 + bb] = src[idx];
    }
    __syncthreads();
    for (int idx = tid; idx < 4096; idx += 256) {
        int bb = idx >> 5, hh = idx & 31;
        out[(size_t)bb * Lseq * Hd + (size_t)t * Hd + h0 + hh] = tile[hh * 129 + bb];
    }
}

// ---------------- final hidden states ----------------
__global__ __launch_bounds__(256) void hn_kernel(float* __restrict__ out)
{
    int idx = blockIdx.x * blockDim.x + threadIdx.x;  // 0..65535
    int layer = idx >> 15;
    int b = (idx >> 8) & 127;
    int h = idx & 255;
    const float* hs = layer ? g_hseq1 : g_hseq0;
    out[(size_t)Bsz * Lseq * Hd + idx] =
        hs[(size_t)(Lseq - 1) * (Hd * Bsz) + (size_t)h * Bsz + b];
}

// ---------------- launcher ----------------
extern "C" void kernel_launch(void* const* d_in, const int* in_sizes, int n_in,
                              void* d_out, int out_size)
{
    const float* x     = (const float*)d_in[0];
    const float* h0    = (const float*)d_in[1];
    const float* w_ih0 = (const float*)d_in[2];
    const float* w_hh0 = (const float*)d_in[3];
    const float* b_ih0 = (const float*)d_in[4];
    const float* b_hh0 = (const float*)d_in[5];
    const float* w_ih1 = (const float*)d_in[6];
    const float* w_hh1 = (const float*)d_in[7];
    const float* b_ih1 = (const float*)d_in[8];
    const float* b_hh1 = (const float*)d_in[9];
    float* out = (float*)d_out;

    const size_t smem = (6192 + 3072) * sizeof(u64)
                      + (8192 + 32) * sizeof(float)
                      + 32 * sizeof(unsigned);   // 107,136 B -> 2 blocks/SM
    cudaFuncSetAttribute(gru_mega_kernel,
                         cudaFuncAttributeMaxDynamicSharedMemorySize, (int)smem);

    epoch_kernel<<<1, 32>>>();
    gi_gemm_kernel<<<dim3(6, Lseq), 256>>>(x, w_ih0, b_ih0);
    // recur0 (0-127) || recur1 (128-255) || gemm1 scavengers (256..3327)
    gru_mega_kernel<<<256 + 3072, 512, smem>>>(w_hh0, b_hh0, w_hh1, b_hh1,
                                               w_ih1, b_ih1, h0);
    transpose_out_kernel<<<dim3(8, Lseq), 256>>>(out);
    if (out_size >= (int)((size_t)Bsz * Lseq * Hd + 2 * Bsz * Hd))
        hn_kernel<<<256, 256>>>(out);
}